// round 17
// baseline (speedup 1.0000x reference)
#include <cuda_runtime.h>
#include <cuda_bf16.h>
#include <cstdint>
#include <math.h>

// Fixed problem sizes
#define M_TOTAL 8192      // B*S = 4*2048
#define N_TOTAL 4096      // OUT
#define K_TOTAL 4096      // IN

// ---- device-global scratch (allocation-free) ----
__device__ __align__(16) int8_t g_xq[(size_t)M_TOTAL * K_TOTAL];  // quantized x
__device__ __align__(16) int8_t g_cb[(size_t)N_TOTAL * K_TOTAL];  // normalized int8 weights
__device__ float g_sx[M_TOTAL];                                   // per-row scale absmax/127
__device__ int   g_cb_mode;   // 0=int8 packed, 1=int32, 2=fp32, 3=bf16

// Work split inside each 128x128 tile: IMMA engine n 0..71, dp4a engine n 72..127
#define N_IMMA 72
#define N_DP4A 56

// ============================================================================
// Helpers (base-ISA only)
// ============================================================================
__device__ __forceinline__ uint32_t smem_u32(const void* p) {
    uint32_t a;
    asm("{ .reg .u64 t; cvta.to.shared.u64 t, %1; cvt.u32.u64 %0, t; }"
        : "=r"(a) : "l"(p));
    return a;
}
__device__ __forceinline__ void cp16(uint32_t dst, const void* src) {
    asm volatile("cp.async.cg.shared.global [%0], [%1], 16;" :: "r"(dst), "l"(src));
}
__device__ __forceinline__ void cp_commit() {
    asm volatile("cp.async.commit_group;" ::: "memory");
}
__device__ __forceinline__ void cp_wait0() {
    asm volatile("cp.async.wait_group 0;" ::: "memory");
}
__device__ __forceinline__ void ldsm_x4(uint32_t* r, uint32_t addr) {
    asm volatile("ldmatrix.sync.aligned.m8n8.x4.shared.b16 {%0,%1,%2,%3}, [%4];"
                 : "=r"(r[0]), "=r"(r[1]), "=r"(r[2]), "=r"(r[3]) : "r"(addr));
}
__device__ __forceinline__ void ldsm_x2(uint32_t& r0, uint32_t& r1, uint32_t addr) {
    asm volatile("ldmatrix.sync.aligned.m8n8.x2.shared.b16 {%0,%1}, [%2];"
                 : "=r"(r0), "=r"(r1) : "r"(addr));
}
__device__ __forceinline__ void mma_s8(int* c, const uint32_t* a, const uint32_t* b) {
    asm volatile("mma.sync.aligned.m16n8k32.row.col.s32.s8.s8.s32 "
                 "{%0,%1,%2,%3}, {%4,%5,%6,%7}, {%8,%9}, {%0,%1,%2,%3};"
                 : "+r"(c[0]), "+r"(c[1]), "+r"(c[2]), "+r"(c[3])
                 : "r"(a[0]), "r"(a[1]), "r"(a[2]), "r"(a[3]),
                   "r"(b[0]), "r"(b[1]));
}
__device__ __forceinline__ void barx(int id, int cnt) {
    asm volatile("bar.sync %0, %1;" :: "r"(id), "r"(cnt) : "memory");
}
// swizzled byte offset for [rows x 64B] tiles (proven in R11)
__device__ __forceinline__ uint32_t swoff(int row, int k) {
    return (uint32_t)(row * 64 + k) ^ (((((uint32_t)row) >> 1) & 7u) << 4);
}

// ============================================================================
// Kernel 0a: detect CB storage dtype (proven)
// ============================================================================
__global__ void detect_cb_kernel(const void* __restrict__ cb) {
    __shared__ int ok_i32, ok_f32, ok_bf16;
    if (threadIdx.x == 0) { ok_i32 = 1; ok_f32 = 1; ok_bf16 = 1; }
    __syncthreads();
    const int tid = threadIdx.x;
    bool my_i32 = true, my_f32 = true, my_bf16 = true;
#pragma unroll
    for (int t = 0; t < 16; t++) {
        const int idx = tid + t * 256;
        const int vi = ((const int*)cb)[idx];
        if (vi < -127 || vi > 127) my_i32 = false;
        const float vf = ((const float*)cb)[idx];
        if (!(isfinite(vf) && fabsf(vf) <= 127.0f && vf == rintf(vf))) my_f32 = false;
        const unsigned short h = ((const unsigned short*)cb)[idx];
        __nv_bfloat16 bh = *reinterpret_cast<const __nv_bfloat16*>(&h);
        const float vb = __bfloat162float(bh);
        if (!(isfinite(vb) && fabsf(vb) <= 127.0f && vb == rintf(vb))) my_bf16 = false;
    }
    if (!my_i32)  ok_i32 = 0;
    if (!my_f32)  ok_f32 = 0;
    if (!my_bf16) ok_bf16 = 0;
    __syncthreads();
    if (tid == 0) {
        int mode = 0;
        if      (ok_i32)  mode = 1;
        else if (ok_f32)  mode = 2;
        else if (ok_bf16) mode = 3;
        g_cb_mode = mode;
    }
}

// ============================================================================
// Kernel 0b: normalize CB into packed int8 (proven)
// ============================================================================
__global__ __launch_bounds__(256) void convert_cb_kernel(const void* __restrict__ cb) {
    const int mode = g_cb_mode;
    const size_t q = (size_t)blockIdx.x * 256 + threadIdx.x;
    int* dst = reinterpret_cast<int*>(g_cb);
    if (mode == 0) {
        dst[q] = ((const int*)cb)[q];
    } else if (mode == 1) {
        const int4 v = ((const int4*)cb)[q];
        dst[q] = (int)((unsigned)(v.x & 0xff) | ((unsigned)(v.y & 0xff) << 8) |
                       ((unsigned)(v.z & 0xff) << 16) | ((unsigned)(v.w & 0xff) << 24));
    } else if (mode == 2) {
        const float4 v = ((const float4*)cb)[q];
        const int a = __float2int_rn(v.x) & 0xff, b = __float2int_rn(v.y) & 0xff;
        const int c = __float2int_rn(v.z) & 0xff, d = __float2int_rn(v.w) & 0xff;
        dst[q] = a | (b << 8) | (c << 16) | (d << 24);
    } else {
        const __nv_bfloat162* p = reinterpret_cast<const __nv_bfloat162*>(cb);
        const __nv_bfloat162 v0 = p[q * 2], v1 = p[q * 2 + 1];
        const int a = __float2int_rn(__bfloat162float(v0.x)) & 0xff;
        const int b = __float2int_rn(__bfloat162float(v0.y)) & 0xff;
        const int c = __float2int_rn(__bfloat162float(v1.x)) & 0xff;
        const int d = __float2int_rn(__bfloat162float(v1.y)) & 0xff;
        dst[q] = a | (b << 8) | (c << 16) | (d << 24);
    }
}

// ============================================================================
// Kernel 1: per-row dynamic int8 quantization of x (proven)
// ============================================================================
__global__ __launch_bounds__(256) void quant_v2(const float* __restrict__ x) {
    __shared__ float smax[256];
    const int row = blockIdx.x;
    const int tid = threadIdx.x;
    const float* xr = x + (size_t)row * K_TOTAL;
    float v[16];
    float am = 0.0f;
#pragma unroll
    for (int t = 0; t < 16; t++) {
        v[t] = xr[tid + t * 256];
        am = fmaxf(am, fabsf(v[t]));
    }
    smax[tid] = am;
    __syncthreads();
#pragma unroll
    for (int off = 128; off > 0; off >>= 1) {
        if (tid < off) smax[tid] = fmaxf(smax[tid], smax[tid + off]);
        __syncthreads();
    }
    const float s = smax[0] / 127.0f;
    int8_t* q = g_xq + (size_t)row * K_TOTAL;
#pragma unroll
    for (int t = 0; t < 16; t++) q[tid + t * 256] = (int8_t)__float2int_rn(v[t] / s);
    if (tid == 0) g_sx[row] = s;
}

// ============================================================================
// Kernel 2: INTRA-CTA HYBRID GEMM, rebalanced 72/56.
//   warps 0-3 : IMMA (tensor pipe), n 0..71. Asymmetric warp tiles:
//               wn2=0 -> 64x40 (5 frags, incl. ldmatrix.x2), wn2=1 -> 64x32.
//   warps 4-7 : dp4a (fma pipe), n 72..127, 8x7 micro-tile, [KW][58] B smem.
// Independent named barriers; disjoint SMEM.
// ============================================================================
#define BK 64
#define KW 16
#define DB_STRIDE 58   // sDB column stride (conflict-free STS & reads)

__global__ __launch_bounds__(256, 2) void gemm_hybrid5(const float* __restrict__ SCB,
                                                       float* __restrict__ y) {
    __shared__ __align__(16) int8_t sIA[2][128 * BK];       // IMMA A: 2 x 8 KB
    __shared__ __align__(16) int8_t sIB[2][N_IMMA * BK];    // IMMA B: 2 x 4.5 KB
    __shared__ __align__(16) int    sDA[2][KW][128];        // dp4a A: 2 x 8 KB
    __shared__ __align__(16) int    sDB[2][KW][DB_STRIDE];  // dp4a B: 2 x 3.6 KB

    const int tid = threadIdx.x;
    const int bn = blockIdx.x;     // 0..31
    const int bm = blockIdx.y;     // 0..63

    if (tid < 128) {
        // ==================== IMMA half: n 0..71 ====================
        const int wid = tid >> 5;          // 0..3
        const int lane = tid & 31;
        const int wm = wid >> 1;           // m offset wm*64
        const int wn2 = wid & 1;           // n offset wn2*40 (tile 40 or 32 wide)

        // cp.async producer mapping
        // A: 512 16B-chunks (4/thr)
        const int8_t* aSrc[4]; uint32_t aDst[4];
#pragma unroll
        for (int i = 0; i < 4; i++) {
            const int c = tid + i * 128;
            const int r = c >> 2, s = c & 3;
            aSrc[i] = g_xq + (size_t)(bm * 128 + r) * K_TOTAL + s * 16;
            aDst[i] = swoff(r, s * 16);
        }
        // B: 288 chunks (2/thr + third for tid<32)
        const int8_t* bSrc[3]; uint32_t bDst[3];
#pragma unroll
        for (int i = 0; i < 3; i++) {
            const int c = tid + i * 128;
            const int cc = (c < 288) ? c : 0;
            const int r = cc >> 2, s = cc & 3;
            bSrc[i] = g_cb + (size_t)(bn * 128 + r) * K_TOTAL + s * 16;
            bDst[i] = swoff(r, s * 16);
        }
        const bool hasB2 = (tid < 32);

        const uint32_t aSm = smem_u32(&sIA[0][0]);
        const uint32_t bSm = smem_u32(&sIB[0][0]);

        const int q = lane >> 3, lr = lane & 7;
        const int aRowL = wm * 64 + (q & 1) * 8 + lr;
        const int aKL   = (q >> 1) * 16;
        const int bRowL = wn2 * 40 + (q >> 1) * 8 + lr;      // x4 frags (fj 0..3)
        const int bKL   = (q & 1) * 16;
        const int l4 = lane & 15;                            // x2 frag (fj 4, wn2==0)
        const int b2Row = 32 + (l4 & 7);
        const int b2K   = (l4 >> 3) * 16;

        int acc[20][4];
#pragma unroll
        for (int f = 0; f < 20; f++)
#pragma unroll
            for (int r = 0; r < 4; r++) acc[f][r] = 0;

        // preload slab 0 -> buffer 0
#pragma unroll
        for (int i = 0; i < 4; i++) cp16(aSm + aDst[i], aSrc[i]);
#pragma unroll
        for (int i = 0; i < 2; i++) cp16(bSm + bDst[i], bSrc[i]);
        if (hasB2) cp16(bSm + bDst[2], bSrc[2]);
        cp_commit(); cp_wait0();
        barx(1, 128);

        const int NT = K_TOTAL / BK;   // 64
        for (int kt = 0; kt < NT; kt++) {
            const int buf = kt & 1;
            if (kt + 1 < NT) {     // async-load next slab into other buffer
                const uint32_t aN = aSm + (buf ^ 1) * (128 * BK);
                const uint32_t bN = bSm + (buf ^ 1) * (N_IMMA * BK);
                const int off = (kt + 1) * BK;
#pragma unroll
                for (int i = 0; i < 4; i++) cp16(aN + aDst[i], aSrc[i] + off);
#pragma unroll
                for (int i = 0; i < 2; i++) cp16(bN + bDst[i], bSrc[i] + off);
                if (hasB2) cp16(bN + bDst[2], bSrc[2] + off);
                cp_commit();
            }
            const uint32_t aB = aSm + buf * (128 * BK);
            const uint32_t bB = bSm + buf * (N_IMMA * BK);

#pragma unroll
            for (int ks = 0; ks < 2; ks++) {
                uint32_t a[4][4], b[5][2];
#pragma unroll
                for (int fi = 0; fi < 4; fi++)
                    ldsm_x4(a[fi], aB + swoff(aRowL + fi * 16, aKL + ks * 32));
#pragma unroll
                for (int pr = 0; pr < 2; pr++) {
                    uint32_t t4[4];
                    ldsm_x4(t4, bB + swoff(bRowL + pr * 16, bKL + ks * 32));
                    b[pr * 2][0] = t4[0]; b[pr * 2][1] = t4[1];
                    b[pr * 2 + 1][0] = t4[2]; b[pr * 2 + 1][1] = t4[3];
                }
                if (wn2 == 0)   // warp-uniform branch
                    ldsm_x2(b[4][0], b[4][1], bB + swoff(b2Row, b2K + ks * 32));
#pragma unroll
                for (int fi = 0; fi < 4; fi++)
#pragma unroll
                    for (int fj = 0; fj < 5; fj++)
                        if (fj < 4 || wn2 == 0)   // warp-uniform
                            mma_s8(acc[fi * 5 + fj], a[fi], b[fj]);
            }

            cp_wait0();
            barx(1, 128);
        }

        // epilogue
        const int g = lane >> 2, tg = lane & 3;
        float scb[10];
#pragma unroll
        for (int fj = 0; fj < 5; fj++) {
            if (fj < 4 || wn2 == 0) {
                const int n = bn * 128 + wn2 * 40 + fj * 8 + tg * 2;
                scb[fj * 2]     = SCB[n]     * (1.0f / 127.0f);
                scb[fj * 2 + 1] = SCB[n + 1] * (1.0f / 127.0f);
            }
        }
#pragma unroll
        for (int fi = 0; fi < 4; fi++) {
#pragma unroll
            for (int h = 0; h < 2; h++) {
                const int m = bm * 128 + wm * 64 + fi * 16 + g + h * 8;
                const float sm = g_sx[m];
                float* yr = y + (size_t)m * N_TOTAL + bn * 128 + wn2 * 40;
#pragma unroll
                for (int fj = 0; fj < 5; fj++) {
                    if (fj < 4 || wn2 == 0) {
                        const int* c = acc[fi * 5 + fj];
                        float2 o;
                        o.x = (float)c[h * 2]     * sm * scb[fj * 2];
                        o.y = (float)c[h * 2 + 1] * sm * scb[fj * 2 + 1];
                        *reinterpret_cast<float2*>(yr + fj * 8 + tg * 2) = o;
                    }
                }
            }
        }
    } else {
        // ==================== dp4a half: n 72..127 (56 cols, 8x7 micro) ====================
        const int t = tid - 128;           // 0..127

        // producer: A 512 chunks (4/thr), B 224 chunks (1/thr + second for t<96)
        const int8_t* aP[4]; int aRow[4], aSeg[4];
#pragma unroll
        for (int i = 0; i < 4; i++) {
            const int c = t + i * 128;
            aRow[i] = c >> 2; aSeg[i] = c & 3;
            aP[i] = g_xq + (size_t)(bm * 128 + aRow[i]) * K_TOTAL + aSeg[i] * 16;
        }
        const int8_t* bP[2]; int bRow[2], bSeg[2];
#pragma unroll
        for (int i = 0; i < 2; i++) {
            const int c = t + i * 128;
            const int cc = (c < 224) ? c : 0;
            bRow[i] = cc >> 2; bSeg[i] = cc & 3;
            bP[i] = g_cb + (size_t)(bn * 128 + N_IMMA + bRow[i]) * K_TOTAL + bSeg[i] * 16;
        }
        const bool hasB1 = (t < 96);
        const int aRS[4] = { aRow[0] ^ (aSeg[0] << 3), aRow[1] ^ (aSeg[1] << 3),
                             aRow[2] ^ (aSeg[2] << 3), aRow[3] ^ (aSeg[3] << 3) };

        int acc[8][7];
#pragma unroll
        for (int i = 0; i < 8; i++)
#pragma unroll
            for (int j = 0; j < 7; j++) acc[i][j] = 0;

        const int ty = t >> 3;    // 0..15 -> rows ty*8..+7
        const int tx = t & 7;     // 0..7  -> local cols tx*7..+6

        int4 av[4], bv[2];
        // preload kt=0 -> buffer 0
#pragma unroll
        for (int i = 0; i < 4; i++) av[i] = *reinterpret_cast<const int4*>(aP[i]);
        bv[0] = *reinterpret_cast<const int4*>(bP[0]);
        if (hasB1) bv[1] = *reinterpret_cast<const int4*>(bP[1]);
#pragma unroll
        for (int i = 0; i < 4; i++) {
            sDA[0][aSeg[i] * 4 + 0][aRS[i]] = av[i].x;
            sDA[0][aSeg[i] * 4 + 1][aRS[i]] = av[i].y;
            sDA[0][aSeg[i] * 4 + 2][aRS[i]] = av[i].z;
            sDA[0][aSeg[i] * 4 + 3][aRS[i]] = av[i].w;
        }
        sDB[0][bSeg[0] * 4 + 0][bRow[0]] = bv[0].x;
        sDB[0][bSeg[0] * 4 + 1][bRow[0]] = bv[0].y;
        sDB[0][bSeg[0] * 4 + 2][bRow[0]] = bv[0].z;
        sDB[0][bSeg[0] * 4 + 3][bRow[0]] = bv[0].w;
        if (hasB1) {
            sDB[0][bSeg[1] * 4 + 0][bRow[1]] = bv[1].x;
            sDB[0][bSeg[1] * 4 + 1][bRow[1]] = bv[1].y;
            sDB[0][bSeg[1] * 4 + 2][bRow[1]] = bv[1].z;
            sDB[0][bSeg[1] * 4 + 3][bRow[1]] = bv[1].w;
        }
        barx(2, 128);

        const int NT = K_TOTAL / BK;   // 64
        for (int kt = 0; kt < NT; kt++) {
            const int buf = kt & 1;
            if (kt + 1 < NT) {   // register prefetch
#pragma unroll
                for (int i = 0; i < 4; i++)
                    av[i] = *reinterpret_cast<const int4*>(aP[i] + (kt + 1) * BK);
                bv[0] = *reinterpret_cast<const int4*>(bP[0] + (kt + 1) * BK);
                if (hasB1) bv[1] = *reinterpret_cast<const int4*>(bP[1] + (kt + 1) * BK);
            }

#pragma unroll
            for (int kw = 0; kw < KW; kw++) {
                const int sgrp = kw >> 2;
                const int* ap = &sDA[buf][kw][(ty ^ sgrp) << 3];
                const int4 a0 = *reinterpret_cast<const int4*>(ap);
                const int4 a1 = *reinterpret_cast<const int4*>(ap + 4);
                const int a[8] = {a0.x, a0.y, a0.z, a0.w, a1.x, a1.y, a1.z, a1.w};
                int b[7];
#pragma unroll
                for (int j = 0; j < 7; j++) b[j] = sDB[buf][kw][tx * 7 + j];
#pragma unroll
                for (int i = 0; i < 8; i++)
#pragma unroll
                    for (int j = 0; j < 7; j++)
                        acc[i][j] = __dp4a(a[i], b[j], acc[i][j]);
            }

            if (kt + 1 < NT) {
                const int nb = buf ^ 1;
#pragma unroll
                for (int i = 0; i < 4; i++) {
                    sDA[nb][aSeg[i] * 4 + 0][aRS[i]] = av[i].x;
                    sDA[nb][aSeg[i] * 4 + 1][aRS[i]] = av[i].y;
                    sDA[nb][aSeg[i] * 4 + 2][aRS[i]] = av[i].z;
                    sDA[nb][aSeg[i] * 4 + 3][aRS[i]] = av[i].w;
                }
                sDB[nb][bSeg[0] * 4 + 0][bRow[0]] = bv[0].x;
                sDB[nb][bSeg[0] * 4 + 1][bRow[0]] = bv[0].y;
                sDB[nb][bSeg[0] * 4 + 2][bRow[0]] = bv[0].z;
                sDB[nb][bSeg[0] * 4 + 3][bRow[0]] = bv[0].w;
                if (hasB1) {
                    sDB[nb][bSeg[1] * 4 + 0][bRow[1]] = bv[1].x;
                    sDB[nb][bSeg[1] * 4 + 1][bRow[1]] = bv[1].y;
                    sDB[nb][bSeg[1] * 4 + 2][bRow[1]] = bv[1].z;
                    sDB[nb][bSeg[1] * 4 + 3][bRow[1]] = bv[1].w;
                }
                barx(2, 128);
            }
        }

        // epilogue
        const int m0 = bm * 128 + ty * 8;
        const int n0 = bn * 128 + N_IMMA + tx * 7;
        float scb[7];
#pragma unroll
        for (int j = 0; j < 7; j++) scb[j] = SCB[n0 + j] * (1.0f / 127.0f);
#pragma unroll
        for (int i = 0; i < 8; i++) {
            const float sm = g_sx[m0 + i];
            float* yr = y + (size_t)(m0 + i) * N_TOTAL + n0;
#pragma unroll
            for (int j = 0; j < 7; j++) {
                yr[j] = (float)acc[i][j] * sm * scb[j];
            }
        }
    }
}

// ============================================================================
// Launch. Inputs bound by element count:
//   x: 33,554,432   CB: 16,777,216 (dtype auto-detected)   SCB: 4,096
// ============================================================================
extern "C" void kernel_launch(void* const* d_in, const int* in_sizes, int n_in,
                              void* d_out, int out_size) {
    const float* x   = nullptr;
    const void*  CB  = nullptr;
    const float* SCB = nullptr;
    for (int i = 0; i < n_in; i++) {
        if (in_sizes[i] == 33554432)      x   = (const float*)d_in[i];
        else if (in_sizes[i] == 16777216) CB  = d_in[i];
        else if (in_sizes[i] == 4096)     SCB = (const float*)d_in[i];
    }
    float* y = (float*)d_out;

    detect_cb_kernel<<<1, 256>>>(CB);
    convert_cb_kernel<<<(N_TOTAL * K_TOTAL / 4) / 256, 256>>>(CB);
    quant_v2<<<M_TOTAL, 256>>>(x);
    dim3 grid(N_TOTAL / 128, M_TOTAL / 128);   // 32 x 64 = 2048 CTAs
    gemm_hybrid5<<<grid, 256>>>(SCB, y);
}